// round 15
// baseline (speedup 1.0000x reference)
#include <cuda_runtime.h>
#include <cuda_fp16.h>
#include <math.h>
#include <stdint.h>

// Problem constants
#define Bq   2
#define Sq   2048
#define DM   1024
#define Hh   16
#define HD   64
#define MEMN 1000
#define KTOT 10

// ---------------- device scratch (fp16 frag-major operands) ----------------
__device__ unsigned short g_q[Bq * Hh * Sq * HD];    // A-frag fp16 per (b,h,qtile)
__device__ unsigned short g_k[Bq * Hh * Sq * HD];    // QK B-frag fp16 per (b,h)
__device__ unsigned short g_v[Bq * Hh * Sq * HD];    // PV B-frag fp16 per (b,h)
__device__ unsigned short g_att[Bq * Sq * DM];       // A-frag fp16 (flash -> gemm_o)
__device__ unsigned short g_wt[4 * DM * DM];         // B-frag fp16 weights
__device__ unsigned short g_ai[Bq * Sq * DM];        // A-frag fp16 inputs
__device__ float g_ret[Bq * KTOT * DM];
__device__ float g_sims[Bq * MEMN];
__device__ float g_klast[Bq * DM];                   // UNROUNDED last-token key

// ---------------- helpers ----------------
__device__ __forceinline__ uint32_t smem_u32(const void* p) {
    uint32_t a;
    asm("{ .reg .u64 t; cvta.to.shared.u64 t, %1; cvt.u32.u64 %0, t; }" : "=r"(a) : "l"(p));
    return a;
}
__device__ __forceinline__ uint32_t pkh2(float lo, float hi) {
    __half2 h = __floats2half2_rn(lo, hi);
    return *(uint32_t*)&h;
}
__device__ __forceinline__ void mma16(float* c, const uint32_t* a, const uint32_t* b) {
    asm("mma.sync.aligned.m16n8k16.row.col.f32.f16.f16.f32 "
        "{%0,%1,%2,%3},{%4,%5,%6,%7},{%8,%9},{%0,%1,%2,%3};"
        : "+f"(c[0]), "+f"(c[1]), "+f"(c[2]), "+f"(c[3])
        : "r"(a[0]), "r"(a[1]), "r"(a[2]), "r"(a[3]), "r"(b[0]), "r"(b[1]));
}
__device__ __forceinline__ void cpa16(uint32_t d, const void* g) {
    asm volatile("cp.async.cg.shared.global [%0], [%1], 16;" :: "r"(d), "l"(g) : "memory");
}
#define CP_COMMIT() asm volatile("cp.async.commit_group;" ::: "memory")

// V PV-B-frag half index for (key s, dim d) within one (b,h)
__device__ __forceinline__ size_t vfrag16(int s, int d) {
    return ((((size_t)(s >> 4) * 8 + (d >> 3)) * 32 + (d & 7) * 4 + ((s & 7) >> 1)) * 2
            + ((s >> 3) & 1)) * 2 + (s & 1);
}

// ---------------- prep: fp32 inputs -> fp16 A-frag-major -------------------
__global__ __launch_bounds__(256) void prep_a(const float* __restrict__ A,
                                              unsigned short* __restrict__ D)
{
    int gt = blockIdx.x * 256 + threadIdx.x;      // (tile, lane)
    int tile = gt >> 5, lane = gt & 31;
    int mt = tile >> 6, kt = tile & 63;
    int m = mt * 16 + (lane >> 2), k = kt * 16 + (lane & 3) * 2;
    float2 a0 = *(const float2*)&A[(size_t)m * DM + k];
    float2 a1 = *(const float2*)&A[(size_t)(m + 8) * DM + k];
    float2 a2 = *(const float2*)&A[(size_t)m * DM + k + 8];
    float2 a3 = *(const float2*)&A[(size_t)(m + 8) * DM + k + 8];
    uint4 o;
    o.x = pkh2(a0.x, a0.y);
    o.y = pkh2(a1.x, a1.y);
    o.z = pkh2(a2.x, a2.y);
    o.w = pkh2(a3.x, a3.y);
    ((uint4*)D)[gt] = o;
}

// ---------------- weights -> fp16 B-frag-major -----------------------------
__global__ __launch_bounds__(256) void transpose_w(const float* __restrict__ W0,
                                                   const float* __restrict__ W1,
                                                   const float* __restrict__ W2,
                                                   const float* __restrict__ W3,
                                                   unsigned short* __restrict__ WT)
{
    __shared__ float t[32][33];
    int z = blockIdx.z;
    const float* W = (z == 0) ? W0 : (z == 1) ? W1 : (z == 2) ? W2 : W3;
    unsigned short* D = WT + (size_t)z * DM * DM;
    int x = blockIdx.x * 32, y = blockIdx.y * 32;   // x = n0, y = k0
    int tid = threadIdx.x;
    int tx = tid & 31, ty = tid >> 5;
    for (int rr = ty; rr < 32; rr += 8)
        t[rr][tx] = W[(size_t)(y + rr) * DM + x + tx];   // t[k_local][n_local]
    __syncthreads();
    int nt_l = tid >> 6, kt_l = (tid >> 5) & 1, lane = tid & 31;
    int r = lane >> 2, cc = lane & 3;
    int n_l = nt_l * 8 + r;
    int kb = kt_l * 16 + 2 * cc;
    uint2 o;
    o.x = pkh2(t[kb][n_l],     t[kb + 1][n_l]);
    o.y = pkh2(t[kb + 8][n_l], t[kb + 9][n_l]);
    ((uint2*)D)[(((size_t)(x >> 3) + nt_l) * 64 + (y >> 4) + kt_l) * 32 + lane] = o;
}

// ---------------- fp16 frag-major cp.async mma.sync GEMM -------------------
// tile 128x128, K-slab 64 (4 k-instructions), 3 stages x 32KB
#define GNIT   (DM / 64)          // 16
#define GSTG_B 32768
#define GSMEM_BYTES (3 * GSTG_B)

// mode: 0 = fp32 row-major out (gemm_o), 1 = Q frag, 2 = K frag (+klast), 3 = V frag
__device__ __forceinline__ void gemm_body(const unsigned short* __restrict__ A16,
                                          const unsigned short* __restrict__ W16,
                                          void* __restrict__ Cout,
                                          int mode, float* klast, float* dsm)
{
    uint32_t sbase = smem_u32(dsm);
    int tid = threadIdx.x, lane = tid & 31, wid = tid >> 5;
    int wm = wid & 3, wn = wid >> 2;
    int m0 = blockIdx.y * 128, n0 = blockIdx.x * 128;
    int r = lane >> 2;

    // staging: A = 8 chunks of 2KB (per mtile, 4 ktiles); B = 16 chunks of 1KB
    int ca = tid >> 5, ua = tid & 31;
    int cbk = tid >> 4, ub = tid & 15;
    const char* gA = (const char*)A16 + ((size_t)((m0 >> 4) + ca) * 64) * 512 + (size_t)ua * 64;
    const char* gB = (const char*)W16 + ((size_t)((n0 >> 3) + cbk) * 64) * 256 + (size_t)ub * 64;
    uint32_t dA = sbase + (uint32_t)(ca * 2048 + ua * 64);
    uint32_t dB = sbase + 16384u + (uint32_t)(cbk * 1024 + ub * 64);

    float acc[2][8][4];
#pragma unroll
    for (int i = 0; i < 2; i++)
#pragma unroll
        for (int j = 0; j < 8; j++)
#pragma unroll
            for (int t = 0; t < 4; t++) acc[i][j][t] = 0.f;

#pragma unroll
    for (int s = 0; s < 2; s++) {
        uint32_t so = (uint32_t)s * GSTG_B;
#pragma unroll
        for (int j = 0; j < 4; j++) {
            cpa16(dA + so + j * 16, gA + (size_t)s * 2048 + j * 16);
            cpa16(dB + so + j * 16, gB + (size_t)s * 1024 + j * 16);
        }
        CP_COMMIT();
    }

    for (int it = 0; it < GNIT; ++it) {
        if (it + 1 < GNIT) asm volatile("cp.async.wait_group 1;" ::: "memory");
        else               asm volatile("cp.async.wait_group 0;" ::: "memory");
        __syncthreads();
        if (it + 2 < GNIT) {
            int s = it + 2;
            uint32_t so = (uint32_t)(s % 3) * GSTG_B;
#pragma unroll
            for (int j = 0; j < 4; j++) {
                cpa16(dA + so + j * 16, gA + (size_t)s * 2048 + j * 16);
                cpa16(dB + so + j * 16, gB + (size_t)s * 1024 + j * 16);
            }
            CP_COMMIT();
        }

        const uint4* As4 = (const uint4*)((char*)dsm + (it % 3) * GSTG_B);
        const uint2* Bs2 = (const uint2*)((char*)dsm + (it % 3) * GSTG_B + 16384);

#pragma unroll
        for (int ktl = 0; ktl < 4; ktl++) {
            uint4 af[2];
#pragma unroll
            for (int i = 0; i < 2; i++)
                af[i] = As4[((wm * 2 + i) * 4 + ktl) * 32 + lane];
            uint2 bf[8];
#pragma unroll
            for (int j = 0; j < 8; j++)
                bf[j] = Bs2[((wn * 8 + j) * 4 + ktl) * 32 + lane];
#pragma unroll
            for (int i = 0; i < 2; i++)
#pragma unroll
                for (int j = 0; j < 8; j++)
                    mma16(acc[i][j], (const uint32_t*)&af[i], (const uint32_t*)&bf[j]);
        }
    }

    int c2 = (lane & 3) * 2;
#pragma unroll
    for (int i = 0; i < 2; i++) {
#pragma unroll
        for (int j = 0; j < 8; j++) {
            int row0 = m0 + wm * 32 + i * 16 + r;
            int col  = n0 + wn * 64 + j * 8 + c2;
            float a0 = acc[i][j][0], a1 = acc[i][j][1];
            float a2 = acc[i][j][2], a3 = acc[i][j][3];
            if (mode == 0) {
                float* C = (float*)Cout;
                *(float2*)&C[(size_t)row0 * DM + col]       = make_float2(a0, a1);
                *(float2*)&C[(size_t)(row0 + 8) * DM + col] = make_float2(a2, a3);
            } else {
                int bx = row0 >> 11, s0 = row0 & 2047;
                int h = col >> 6, hd = col & 63;
                unsigned short* base = (unsigned short*)Cout + (size_t)(bx * Hh + h) * (Sq * HD);
                if (mode == 1) {
                    uint32_t* qh = (uint32_t*)base;
                    size_t qi = (((size_t)(s0 >> 4) * 4 + (hd >> 4)) * 32 + lane) * 4
                              + ((hd >> 3) & 1) * 2;
                    qh[qi]     = pkh2(a0, a1);
                    qh[qi + 1] = pkh2(a2, a3);
                } else if (mode == 2) {
                    uint32_t* kh = (uint32_t*)base;
                    int e = (hd >> 3) & 1;
                    kh[(((size_t)(s0 >> 3) * 4 + (hd >> 4)) * 32 + lane) * 2 + e] = pkh2(a0, a1);
                    kh[((((size_t)(s0 >> 3) + 1) * 4 + (hd >> 4)) * 32 + lane) * 2 + e] = pkh2(a2, a3);
                    if (klast && s0 + 8 == Sq - 1)
                        *(float2*)&klast[bx * DM + col] = make_float2(a2, a3);
                } else {
                    base[vfrag16(s0, col & 63)]           = __half_as_ushort(__float2half_rn(a0));
                    base[vfrag16(s0, (col & 63) + 1)]     = __half_as_ushort(__float2half_rn(a1));
                    base[vfrag16(s0 + 8, col & 63)]       = __half_as_ushort(__float2half_rn(a2));
                    base[vfrag16(s0 + 8, (col & 63) + 1)] = __half_as_ushort(__float2half_rn(a3));
                }
            }
        }
    }
}

__global__ void __launch_bounds__(256, 2) gemm_qkv(const unsigned short* __restrict__ A,
                                                   const unsigned short* __restrict__ WT,
                                                   unsigned short* q, unsigned short* k,
                                                   unsigned short* v, float* klast)
{
    extern __shared__ float dsm[];
    int z = blockIdx.z;
    unsigned short* C = (z == 0) ? q : (z == 1) ? k : v;
    gemm_body(A, WT + (size_t)z * DM * DM, C, z + 1, (z == 1) ? klast : (float*)0, dsm);
}

__global__ void __launch_bounds__(256, 2) gemm_o(const unsigned short* __restrict__ A,
                                                 const unsigned short* __restrict__ WT,
                                                 float* __restrict__ C)
{
    extern __shared__ float dsm[];
    gemm_body(A, WT, C, 0, (float*)0, dsm);
}

// ---------------- retrieval: sims (warp per event) ------------------------
__global__ __launch_bounds__(256) void retrieve_sims(const float* __restrict__ klast,
                                                     const float* __restrict__ events,
                                                     float* __restrict__ sims)
{
    int b = blockIdx.y;
    int tid = threadIdx.x;
    int lane = tid & 31, wid = tid >> 5;
    __shared__ float qs[DM];
    __shared__ float qn_s;

    for (int d = tid; d < DM; d += 256) qs[d] = klast[b * DM + d];
    __syncthreads();
    if (wid == 0) {
        float ps = 0.f;
        for (int d = lane * 4; d < DM; d += 128) {
            float4 t = *(const float4*)&qs[d];
            ps += t.x * t.x + t.y * t.y + t.z * t.z + t.w * t.w;
        }
#pragma unroll
        for (int off = 16; off > 0; off >>= 1) ps += __shfl_down_sync(0xffffffffu, ps, off);
        if (lane == 0) qn_s = sqrtf(ps) + 1e-8f;
    }
    __syncthreads();
    float qnorm = qn_s;

    int e = blockIdx.x * 8 + wid;
    if (e >= MEMN) return;
    const float* ep = events + (size_t)e * DM;
    float dot = 0.f, nn = 0.f;
    for (int d = lane * 4; d < DM; d += 128) {
        float4 ev = *(const float4*)(ep + d);
        float4 qv = *(const float4*)&qs[d];
        dot += qv.x * ev.x + qv.y * ev.y + qv.z * ev.z + qv.w * ev.w;
        nn  += ev.x * ev.x + ev.y * ev.y + ev.z * ev.z + ev.w * ev.w;
    }
#pragma unroll
    for (int off = 16; off > 0; off >>= 1) {
        dot += __shfl_down_sync(0xffffffffu, dot, off);
        nn  += __shfl_down_sync(0xffffffffu, nn, off);
    }
    if (lane == 0) sims[b * MEMN + e] = dot / (qnorm * (sqrtf(nn) + 1e-8f));
}

// ---------------- retrieval: parallel top-k + gather (raw fp32) ------------
__global__ __launch_bounds__(256) void topk_gather(const float* __restrict__ sims,
                                                   const float* __restrict__ events,
                                                   float* __restrict__ ret)
{
    int b = blockIdx.x;
    int tid = threadIdx.x;
    int lane = tid & 31, wid = tid >> 5;
    __shared__ float sv[MEMN];
    __shared__ float wmax[8];
    __shared__ int   widx[8];
    __shared__ int   tidx[KTOT];

    for (int e = tid; e < MEMN; e += 256) sv[e] = sims[b * MEMN + e];
    __syncthreads();

    for (int kk = 0; kk < KTOT; kk++) {
        float bm = -1e30f; int bi = MEMN;
        for (int e = tid; e < MEMN; e += 256) {
            float v = sv[e];
            if (v > bm || (v == bm && e < bi)) { bm = v; bi = e; }
        }
#pragma unroll
        for (int off = 16; off > 0; off >>= 1) {
            float om = __shfl_down_sync(0xffffffffu, bm, off);
            int   oi = __shfl_down_sync(0xffffffffu, bi, off);
            if (om > bm || (om == bm && oi < bi)) { bm = om; bi = oi; }
        }
        if (lane == 0) { wmax[wid] = bm; widx[wid] = bi; }
        __syncthreads();
        if (tid == 0) {
            float gm = wmax[0]; int gi = widx[0];
            for (int w = 1; w < 8; w++) {
                if (wmax[w] > gm || (wmax[w] == gm && widx[w] < gi)) { gm = wmax[w]; gi = widx[w]; }
            }
            tidx[kk] = gi;
            sv[gi] = -1e30f;
        }
        __syncthreads();
    }

    for (int kk = 0; kk < KTOT; kk++) {
        int src = tidx[kk];
        for (int d = tid; d < DM; d += 256)
            ret[((size_t)b * KTOT + kk) * DM + d] = events[(size_t)src * DM + d];
    }
}

// ---------------- flash v11: fp16 mma, 64-key tiles, safe tail wait --------
#define TKF 64
// smem (bytes): K2 4x8KB | V2 4x8KB | Km 2KB | Vm 2KB | CB 1KB
#define OFFB_K2 0
#define OFFB_V2 32768
#define OFFB_KM 65536
#define OFFB_VM 67584
#define OFFB_CB 69632
#define FSMEM_BYTES (OFFB_CB + 1024)

__global__ void __launch_bounds__(256, 2) flash_mma(const float* __restrict__ amask,
                                                    const unsigned short* __restrict__ qh,
                                                    const unsigned short* __restrict__ kh,
                                                    const unsigned short* __restrict__ vh,
                                                    const float* __restrict__ ret,
                                                    unsigned short* __restrict__ att)
{
    extern __shared__ float fsm[];
    unsigned short* KmH = (unsigned short*)((char*)fsm + OFFB_KM);
    unsigned short* VmH = (unsigned short*)((char*)fsm + OFFB_VM);
    float* CB = (float*)((char*)fsm + OFFB_CB);
    uint32_t sbase = smem_u32(fsm);

    int qt = gridDim.x - 1 - blockIdx.x;   // heavy tiles first
    int h = blockIdx.y, b = blockIdx.z;
    int tid = threadIdx.x;
    int lane = tid & 31, w = tid >> 5;
    int r = lane >> 2, cc = lane & 3;
    int i0 = qt * 128;
    const float scale = 0.125f;
    float slope = exp2f(-0.5f * (float)(h + 1));

    const char* kbc = (const char*)(kh + (size_t)(b * Hh + h) * (Sq * HD));
    const char* vbc = (const char*)(vh + (size_t)(b * Hh + h) * (Sq * HD));

    int ntiles = 2 * qt + 2;

    // ---- prologue: stage K/V tiles 0..2 (8KB each; indices always in-range) ----
    uint32_t dK0 = sbase + OFFB_K2 + (uint32_t)tid * 32;
    uint32_t dV0 = sbase + OFFB_V2 + (uint32_t)tid * 32;
#pragma unroll
    for (int s = 0; s < 3; s++) {
        cpa16(dK0 + s * 8192,      kbc + (size_t)s * 8192 + tid * 32);
        cpa16(dK0 + s * 8192 + 16, kbc + (size_t)s * 8192 + tid * 32 + 16);
        cpa16(dV0 + s * 8192,      vbc + (size_t)s * 8192 + tid * 32);
        cpa16(dV0 + s * 8192 + 16, vbc + (size_t)s * 8192 + tid * 32 + 16);
        CP_COMMIT();
    }
    if (tid < 192) CB[(tid >> 6) * 64 + (tid & 63)] =
        (1.0f - amask[b * Sq + tid]) * (-1e9f);

    // ---- Q fragments into registers (coalesced from frag-major) ----
    uint4 aq[4];
    {
        const uint4* qg = (const uint4*)(qh + (size_t)(b * Hh + h) * (Sq * HD)
                                         + (size_t)qt * 8192);
#pragma unroll
        for (int kt = 0; kt < 4; kt++) aq[kt] = qg[(w * 4 + kt) * 32 + lane];
    }

    // ---- memory tile (10 keys + 6 pad) into fp16 frag side buffers ----
    if (tid < 128) {
        int kk = tid >> 3, dseg = (tid & 7) * 8;
        const float* rp = ret + ((size_t)b * KTOT + kk) * DM + h * HD + dseg;
#pragma unroll
        for (int i = 0; i < 8; i++) {
            int d = dseg + i;
            float vv = (kk < KTOT) ? rp[i] : 0.f;
            unsigned short hv = __half_as_ushort(__float2half_rn(vv));
            KmH[((((kk >> 3) * 4 + (d >> 4)) * 32 + (kk & 7) * 4 + ((d & 7) >> 1)) * 2
                 + ((d >> 3) & 1)) * 2 + (d & 1)] = hv;
            VmH[(((d >> 3) * 32 + (d & 7) * 4 + ((kk & 7) >> 1)) * 2
                 + ((kk >> 3) & 1)) * 2 + (kk & 1)] = hv;
        }
    }
    __syncthreads();

    int row_lo = w * 16 + r;
    int ig_lo = i0 + row_lo, ig_hi = ig_lo + 8;

    const uint2* Km2 = (const uint2*)((char*)fsm + OFFB_KM);
    const uint2* Vm2 = (const uint2*)((char*)fsm + OFFB_VM);

    float of[8][4];
#pragma unroll
    for (int f = 0; f < 8; f++)
#pragma unroll
        for (int e = 0; e < 4; e++) of[f][e] = 0.f;
    float m_lo = -1e30f, m_hi = -1e30f, l_lo = 0.f, l_hi = 0.f;

    // ================= memory pass (16 cols) =================
    {
        float sc[2][4];
#pragma unroll
        for (int f = 0; f < 2; f++)
#pragma unroll
            for (int e = 0; e < 4; e++) sc[f][e] = 0.f;
#pragma unroll
        for (int kt = 0; kt < 4; kt++) {
#pragma unroll
            for (int f = 0; f < 2; f++) {
                uint2 bb = Km2[(f * 4 + kt) * 32 + lane];
                mma16(sc[f], (const uint32_t*)&aq[kt], (const uint32_t*)&bb);
            }
        }
        float tl = m_lo, th = m_hi;
#pragma unroll
        for (int f = 0; f < 2; f++) {
            int c0 = f * 8 + 2 * cc;
            float cb0  = (c0 < KTOT) ? 0.f : -1e30f;
            float cb1v = ((c0 + 1) < KTOT) ? 0.f : -1e30f;
            sc[f][0] = fmaf(sc[f][0], scale, cb0);
            sc[f][1] = fmaf(sc[f][1], scale, cb1v);
            sc[f][2] = fmaf(sc[f][2], scale, cb0);
            sc[f][3] = fmaf(sc[f][3], scale, cb1v);
            tl = fmaxf(tl, fmaxf(sc[f][0], sc[f][1]));
            th = fmaxf(th, fmaxf(sc[f][2], sc[f][3]));
        }
        tl = fmaxf(tl, __shfl_xor_sync(0xffffffffu, tl, 1));
        tl = fmaxf(tl, __shfl_xor_sync(0xffffffffu, tl, 2));
        th = fmaxf(th, __shfl_xor_sync(0xffffffffu, th, 1));
        th = fmaxf(th, __shfl_xor_sync(0xffffffffu, th, 2));
        float corr_lo = __expf(m_lo - tl), corr_hi = __expf(m_hi - th);
        l_lo *= corr_lo; l_hi *= corr_hi;
        m_lo = tl; m_hi = th;
        float sl = 0.f, sh = 0.f;
#pragma unroll
        for (int f = 0; f < 2; f++) {
            sc[f][0] = __expf(sc[f][0] - m_lo); sl += sc[f][0];
            sc[f][1] = __expf(sc[f][1] - m_lo); sl += sc[f][1];
            sc[f][2] = __expf(sc[f][2] - m_hi); sh += sc[f][2];
            sc[f][3] = __expf(sc[f][3] - m_hi); sh += sc[f][3];
        }
        sl += __shfl_xor_sync(0xffffffffu, sl, 1);
        sl += __shfl_xor_sync(0xffffffffu, sl, 2);
        sh += __shfl_xor_sync(0xffffffffu, sh, 1);
        sh += __shfl_xor_sync(0xffffffffu, sh, 2);
        l_lo += sl; l_hi += sh;
#pragma unroll
        for (int f = 0; f < 8; f++) {
            of[f][0] *= corr_lo; of[f][1] *= corr_lo;
            of[f][2] *= corr_hi; of[f][3] *= corr_hi;
        }
        uint32_t ap[4];
        ap[0] = pkh2(sc[0][0], sc[0][1]);
        ap[1] = pkh2(sc[0][2], sc[0][3]);
        ap[2] = pkh2(sc[1][0], sc[1][1]);
        ap[3] = pkh2(sc[1][2], sc[1][3]);
#pragma unroll
        for (int f = 0; f < 8; f++) {
            uint2 bv = Vm2[f * 32 + lane];
            mma16(of[f], ap, (const uint32_t*)&bv);
        }
    }

    // ================= seq tiles (64 keys, 4 buffers, safe tail wait) =======
    for (int t = 0; t < ntiles; ++t) {
        int buf = t & 3;
        int j0 = t * TKF;
        if (t + 2 < ntiles)      asm volatile("cp.async.wait_group 2;" ::: "memory");
        else if (t + 1 < ntiles) asm volatile("cp.async.wait_group 1;" ::: "memory");
        else                     asm volatile("cp.async.wait_group 0;" ::: "memory");
        __syncthreads();
        if (t + 3 < ntiles) {
            int tn = t + 3, bufn = tn & 3;
            cpa16(dK0 + bufn * 8192,      kbc + (size_t)tn * 8192 + tid * 32);
            cpa16(dK0 + bufn * 8192 + 16, kbc + (size_t)tn * 8192 + tid * 32 + 16);
            cpa16(dV0 + bufn * 8192,      vbc + (size_t)tn * 8192 + tid * 32);
            cpa16(dV0 + bufn * 8192 + 16, vbc + (size_t)tn * 8192 + tid * 32 + 16);
            CP_COMMIT();
            if (tid < TKF)
                CB[bufn * 64 + tid] = (1.0f - amask[b * Sq + tn * TKF + tid]) * (-1e9f);
        }
        const uint2* Ks2 = (const uint2*)((char*)fsm + OFFB_K2 + buf * 8192);
        const uint2* Vs2 = (const uint2*)((char*)fsm + OFFB_V2 + buf * 8192);
        const float* cb = CB + buf * 64;

        float sc[8][4];
#pragma unroll
        for (int f = 0; f < 8; f++)
#pragma unroll
            for (int e = 0; e < 4; e++) sc[f][e] = 0.f;
#pragma unroll
        for (int kt = 0; kt < 4; kt++) {
#pragma unroll
            for (int f = 0; f < 8; f++) {
                uint2 bb = Ks2[(f * 4 + kt) * 32 + lane];
                mma16(sc[f], (const uint32_t*)&aq[kt], (const uint32_t*)&bb);
            }
        }

        bool causal = (t >= 2 * qt);
        float o0f = (float)(2 * cc);
        float tl = m_lo, th = m_hi;
#pragma unroll
        for (int f = 0; f < 8; f++) {
            int c0 = f * 8 + 2 * cc;
            float cb0 = cb[c0], cb1v = cb[c0 + 1];
            float fl = (float)(ig_lo - j0 - f * 8);
            float s00 = fmaf(sc[f][0], scale, fmaf(slope, fl - o0f, cb0));
            float s01 = fmaf(sc[f][1], scale, fmaf(slope, fl - o0f - 1.0f, cb1v));
            float s10 = fmaf(sc[f][2], scale, fmaf(slope, fl + 8.0f - o0f, cb0));
            float s11 = fmaf(sc[f][3], scale, fmaf(slope, fl + 8.0f - o0f - 1.0f, cb1v));
            if (causal) {
                int jg0 = j0 + c0;
                if (jg0 > ig_lo)     s00 = -1e30f;
                if (jg0 + 1 > ig_lo) s01 = -1e30f;
                if (jg0 > ig_hi)     s10 = -1e30f;
                if (jg0 + 1 > ig_hi) s11 = -1e30f;
            }
            sc[f][0] = s00; sc[f][1] = s01; sc[f][2] = s10; sc[f][3] = s11;
            tl = fmaxf(tl, fmaxf(s00, s01));
            th = fmaxf(th, fmaxf(s10, s11));
        }
        tl = fmaxf(tl, __shfl_xor_sync(0xffffffffu, tl, 1));
        tl = fmaxf(tl, __shfl_xor_sync(0xffffffffu, tl, 2));
        th = fmaxf(th, __shfl_xor_sync(0xffffffffu, th, 1));
        th = fmaxf(th, __shfl_xor_sync(0xffffffffu, th, 2));

        float corr_lo = __expf(m_lo - tl), corr_hi = __expf(m_hi - th);
        l_lo *= corr_lo; l_hi *= corr_hi;
        m_lo = tl; m_hi = th;

        float sl = 0.f, sh = 0.f;
#pragma unroll
        for (int f = 0; f < 8; f++) {
            sc[f][0] = __expf(sc[f][0] - m_lo); sl += sc[f][0];
            sc[f][1] = __expf(sc[f][1] - m_lo); sl += sc[f][1];
            sc[f][2] = __expf(sc[f][2] - m_hi); sh += sc[f][2];
            sc[f][3] = __expf(sc[f][3] - m_hi); sh += sc[f][3];
        }
        sl += __shfl_xor_sync(0xffffffffu, sl, 1);
        sl += __shfl_xor_sync(0xffffffffu, sl, 2);
        sh += __shfl_xor_sync(0xffffffffu, sh, 1);
        sh += __shfl_xor_sync(0xffffffffu, sh, 2);
        l_lo += sl; l_hi += sh;

#pragma unroll
        for (int f = 0; f < 8; f++) {
            of[f][0] *= corr_lo; of[f][1] *= corr_lo;
            of[f][2] *= corr_hi; of[f][3] *= corr_hi;
        }

        // P reuse: C-frags pack directly as fp16 A-frags (4 key-16 groups)
#pragma unroll
        for (int g = 0; g < 4; g++) {
            uint32_t ap[4];
            ap[0] = pkh2(sc[2 * g][0],     sc[2 * g][1]);
            ap[1] = pkh2(sc[2 * g][2],     sc[2 * g][3]);
            ap[2] = pkh2(sc[2 * g + 1][0], sc[2 * g + 1][1]);
            ap[3] = pkh2(sc[2 * g + 1][2], sc[2 * g + 1][3]);
#pragma unroll
            for (int f = 0; f < 8; f++) {
                uint2 bv = Vs2[(g * 8 + f) * 32 + lane];
                mma16(of[f], ap, (const uint32_t*)&bv);
            }
        }
    }

    // ---- finalize: divide by l, fp16 A-frag store for gemm_o ----
    float inv_lo = 1.0f / l_lo, inv_hi = 1.0f / l_hi;
    int mlo = b * Sq + ig_lo;
    uint32_t* atth = (uint32_t*)att;
#pragma unroll
    for (int f = 0; f < 8; f++) {
        int k0 = h * HD + f * 8 + 2 * cc;
        size_t ai = (((size_t)(mlo >> 4) * 64 + (k0 >> 4)) * 32 + lane) * 4
                  + ((k0 >> 3) & 1) * 2;
        atth[ai]     = pkh2(of[f][0] * inv_lo, of[f][1] * inv_lo);
        atth[ai + 1] = pkh2(of[f][2] * inv_hi, of[f][3] * inv_hi);
    }
}

// ---------------- launcher ----------------
extern "C" void kernel_launch(void* const* d_in, const int* in_sizes, int n_in,
                              void* d_out, int out_size)
{
    const float* inputs = (const float*)d_in[0];
    const float* amask  = (const float*)d_in[1];
    const float* Wq     = (const float*)d_in[2];
    const float* Wk     = (const float*)d_in[3];
    const float* Wv     = (const float*)d_in[4];
    const float* Wo     = (const float*)d_in[5];
    const float* events = (const float*)d_in[6];
    float* out = (float*)d_out;

    unsigned short *q, *k, *v, *att, *wt, *ai;
    float *ret, *sims, *klast;
    cudaGetSymbolAddress((void**)&q,     g_q);
    cudaGetSymbolAddress((void**)&k,     g_k);
    cudaGetSymbolAddress((void**)&v,     g_v);
    cudaGetSymbolAddress((void**)&att,   g_att);
    cudaGetSymbolAddress((void**)&ret,   g_ret);
    cudaGetSymbolAddress((void**)&sims,  g_sims);
    cudaGetSymbolAddress((void**)&wt,    g_wt);
    cudaGetSymbolAddress((void**)&ai,    g_ai);
    cudaGetSymbolAddress((void**)&klast, g_klast);

    cudaFuncSetAttribute(gemm_qkv,  cudaFuncAttributeMaxDynamicSharedMemorySize, GSMEM_BYTES);
    cudaFuncSetAttribute(gemm_o,    cudaFuncAttributeMaxDynamicSharedMemorySize, GSMEM_BYTES);
    cudaFuncSetAttribute(flash_mma, cudaFuncAttributeMaxDynamicSharedMemorySize, FSMEM_BYTES);

    prep_a<<<(Bq * Sq / 16) * (DM / 16) * 32 / 256, 256>>>(inputs, ai);
    transpose_w<<<dim3(32, 32, 4), 256>>>(Wq, Wk, Wv, Wo, wt);

    gemm_qkv<<<dim3(8, 32, 3), 256, GSMEM_BYTES>>>(ai, wt, q, k, v, klast);

    retrieve_sims<<<dim3(125, Bq), 256>>>(klast, events, sims);
    topk_gather<<<Bq, 256>>>(sims, events, ret);

    flash_mma<<<dim3(Sq / 128, Hh, Bq), 256, FSMEM_BYTES>>>(amask, q, k, v, ret, att);

    gemm_o<<<dim3(8, 32), 256, GSMEM_BYTES>>>(att, wt + 3 * (size_t)DM * DM, out);
}

// round 16
// speedup vs baseline: 1.0387x; 1.0387x over previous
#include <cuda_runtime.h>
#include <cuda_fp16.h>
#include <math.h>
#include <stdint.h>

// Problem constants
#define Bq   2
#define Sq   2048
#define DM   1024
#define Hh   16
#define HD   64
#define MEMN 1000
#define KTOT 10

// ---------------- device scratch (fp16 frag-major operands) ----------------
__device__ unsigned short g_q[Bq * Hh * Sq * HD];    // A-frag fp16 per (b,h,qtile)
__device__ unsigned short g_k[Bq * Hh * Sq * HD];    // QK B-frag fp16 per (b,h)
__device__ unsigned short g_v[Bq * Hh * Sq * HD];    // PV B-frag fp16 per (b,h)
__device__ unsigned short g_att[Bq * Sq * DM];       // A-frag fp16 (flash -> gemm_o)
__device__ unsigned short g_wt[4 * DM * DM];         // B-frag fp16 weights
__device__ unsigned short g_ai[Bq * Sq * DM];        // A-frag fp16 inputs
__device__ float g_ret[Bq * KTOT * DM];
__device__ float g_sims[Bq * MEMN];
__device__ float g_klast[Bq * DM];                   // UNROUNDED last-token key

// ---------------- helpers ----------------
__device__ __forceinline__ uint32_t smem_u32(const void* p) {
    uint32_t a;
    asm("{ .reg .u64 t; cvta.to.shared.u64 t, %1; cvt.u32.u64 %0, t; }" : "=r"(a) : "l"(p));
    return a;
}
__device__ __forceinline__ uint32_t pkh2(float lo, float hi) {
    __half2 h = __floats2half2_rn(lo, hi);
    return *(uint32_t*)&h;
}
__device__ __forceinline__ void mma16(float* c, const uint32_t* a, const uint32_t* b) {
    asm("mma.sync.aligned.m16n8k16.row.col.f32.f16.f16.f32 "
        "{%0,%1,%2,%3},{%4,%5,%6,%7},{%8,%9},{%0,%1,%2,%3};"
        : "+f"(c[0]), "+f"(c[1]), "+f"(c[2]), "+f"(c[3])
        : "r"(a[0]), "r"(a[1]), "r"(a[2]), "r"(a[3]), "r"(b[0]), "r"(b[1]));
}
__device__ __forceinline__ void cpa16(uint32_t d, const void* g) {
    asm volatile("cp.async.cg.shared.global [%0], [%1], 16;" :: "r"(d), "l"(g) : "memory");
}
#define CP_COMMIT() asm volatile("cp.async.commit_group;" ::: "memory")

// V PV-B-frag half index for (key s, dim d) within one (b,h)
__device__ __forceinline__ size_t vfrag16(int s, int d) {
    return ((((size_t)(s >> 4) * 8 + (d >> 3)) * 32 + (d & 7) * 4 + ((s & 7) >> 1)) * 2
            + ((s >> 3) & 1)) * 2 + (s & 1);
}

// ---------------- prep: fp32 inputs -> fp16 A-frag-major -------------------
__global__ __launch_bounds__(256) void prep_a(const float* __restrict__ A,
                                              unsigned short* __restrict__ D)
{
    int gt = blockIdx.x * 256 + threadIdx.x;      // (tile, lane)
    int tile = gt >> 5, lane = gt & 31;
    int mt = tile >> 6, kt = tile & 63;
    int m = mt * 16 + (lane >> 2), k = kt * 16 + (lane & 3) * 2;
    float2 a0 = *(const float2*)&A[(size_t)m * DM + k];
    float2 a1 = *(const float2*)&A[(size_t)(m + 8) * DM + k];
    float2 a2 = *(const float2*)&A[(size_t)m * DM + k + 8];
    float2 a3 = *(const float2*)&A[(size_t)(m + 8) * DM + k + 8];
    uint4 o;
    o.x = pkh2(a0.x, a0.y);
    o.y = pkh2(a1.x, a1.y);
    o.z = pkh2(a2.x, a2.y);
    o.w = pkh2(a3.x, a3.y);
    ((uint4*)D)[gt] = o;
}

// ---------------- weights -> fp16 B-frag-major -----------------------------
__global__ __launch_bounds__(256) void transpose_w(const float* __restrict__ W0,
                                                   const float* __restrict__ W1,
                                                   const float* __restrict__ W2,
                                                   const float* __restrict__ W3,
                                                   unsigned short* __restrict__ WT)
{
    __shared__ float t[32][33];
    int z = blockIdx.z;
    const float* W = (z == 0) ? W0 : (z == 1) ? W1 : (z == 2) ? W2 : W3;
    unsigned short* D = WT + (size_t)z * DM * DM;
    int x = blockIdx.x * 32, y = blockIdx.y * 32;   // x = n0, y = k0
    int tid = threadIdx.x;
    int tx = tid & 31, ty = tid >> 5;
    for (int rr = ty; rr < 32; rr += 8)
        t[rr][tx] = W[(size_t)(y + rr) * DM + x + tx];   // t[k_local][n_local]
    __syncthreads();
    int nt_l = tid >> 6, kt_l = (tid >> 5) & 1, lane = tid & 31;
    int r = lane >> 2, cc = lane & 3;
    int n_l = nt_l * 8 + r;
    int kb = kt_l * 16 + 2 * cc;
    uint2 o;
    o.x = pkh2(t[kb][n_l],     t[kb + 1][n_l]);
    o.y = pkh2(t[kb + 8][n_l], t[kb + 9][n_l]);
    ((uint2*)D)[(((size_t)(x >> 3) + nt_l) * 64 + (y >> 4) + kt_l) * 32 + lane] = o;
}

// ---------------- fp16 frag-major cp.async mma.sync GEMM -------------------
// tile 128x128, K-slab 32 (2 k-instructions), 4 stages x 16KB
#define GNIT   (DM / 32)          // 32
#define GSTG_B 16384
#define GNSTG  4
#define GSMEM_BYTES (GNSTG * GSTG_B)

// mode: 0 = fp32 row-major out (gemm_o), 1 = Q frag, 2 = K frag (+klast), 3 = V frag
__device__ __forceinline__ void gemm_body(const unsigned short* __restrict__ A16,
                                          const unsigned short* __restrict__ W16,
                                          void* __restrict__ Cout,
                                          int mode, float* klast, float* dsm)
{
    uint32_t sbase = smem_u32(dsm);
    int tid = threadIdx.x, lane = tid & 31, wid = tid >> 5;
    int wm = wid & 3, wn = wid >> 2;
    int m0 = blockIdx.y * 128, n0 = blockIdx.x * 128;
    int r = lane >> 2;

    int ca = tid >> 5, ua = tid & 31;
    int cbk = tid >> 4, ub = tid & 15;
    const char* gA = (const char*)A16 + ((size_t)((m0 >> 4) + ca) * 64) * 512 + (size_t)ua * 32;
    const char* gB = (const char*)W16 + ((size_t)((n0 >> 3) + cbk) * 64) * 256 + (size_t)ub * 32;
    uint32_t dA = sbase + (uint32_t)(ca * 1024 + ua * 32);
    uint32_t dB = sbase + 8192u + (uint32_t)(cbk * 512 + ub * 32);

    float acc[2][8][4];
#pragma unroll
    for (int i = 0; i < 2; i++)
#pragma unroll
        for (int j = 0; j < 8; j++)
#pragma unroll
            for (int t = 0; t < 4; t++) acc[i][j][t] = 0.f;

#pragma unroll
    for (int s = 0; s < GNSTG - 1; s++) {
        uint32_t so = (uint32_t)s * GSTG_B;
        cpa16(dA + so,      gA + (size_t)s * 1024);
        cpa16(dA + so + 16, gA + (size_t)s * 1024 + 16);
        cpa16(dB + so,      gB + (size_t)s * 512);
        cpa16(dB + so + 16, gB + (size_t)s * 512 + 16);
        CP_COMMIT();
    }

    for (int it = 0; it < GNIT; ++it) {
        if (it + 2 < GNIT)      asm volatile("cp.async.wait_group 2;" ::: "memory");
        else if (it + 1 < GNIT) asm volatile("cp.async.wait_group 1;" ::: "memory");
        else                    asm volatile("cp.async.wait_group 0;" ::: "memory");
        __syncthreads();
        if (it + GNSTG - 1 < GNIT) {
            int s = it + GNSTG - 1;
            uint32_t so = (uint32_t)(s % GNSTG) * GSTG_B;
            cpa16(dA + so,      gA + (size_t)s * 1024);
            cpa16(dA + so + 16, gA + (size_t)s * 1024 + 16);
            cpa16(dB + so,      gB + (size_t)s * 512);
            cpa16(dB + so + 16, gB + (size_t)s * 512 + 16);
            CP_COMMIT();
        }

        const uint4* As4 = (const uint4*)((char*)dsm + (it % GNSTG) * GSTG_B);
        const uint2* Bs2 = (const uint2*)((char*)dsm + (it % GNSTG) * GSTG_B + 8192);

#pragma unroll
        for (int ktl = 0; ktl < 2; ktl++) {
            uint4 af[2];
#pragma unroll
            for (int i = 0; i < 2; i++)
                af[i] = As4[((wm * 2 + i) * 2 + ktl) * 32 + lane];
            uint2 bf[8];
#pragma unroll
            for (int j = 0; j < 8; j++)
                bf[j] = Bs2[((wn * 8 + j) * 2 + ktl) * 32 + lane];
#pragma unroll
            for (int i = 0; i < 2; i++)
#pragma unroll
                for (int j = 0; j < 8; j++)
                    mma16(acc[i][j], (const uint32_t*)&af[i], (const uint32_t*)&bf[j]);
        }
    }

    int c2 = (lane & 3) * 2;
#pragma unroll
    for (int i = 0; i < 2; i++) {
#pragma unroll
        for (int j = 0; j < 8; j++) {
            int row0 = m0 + wm * 32 + i * 16 + r;
            int col  = n0 + wn * 64 + j * 8 + c2;
            float a0 = acc[i][j][0], a1 = acc[i][j][1];
            float a2 = acc[i][j][2], a3 = acc[i][j][3];
            if (mode == 0) {
                float* C = (float*)Cout;
                *(float2*)&C[(size_t)row0 * DM + col]       = make_float2(a0, a1);
                *(float2*)&C[(size_t)(row0 + 8) * DM + col] = make_float2(a2, a3);
            } else {
                int bx = row0 >> 11, s0 = row0 & 2047;
                int h = col >> 6, hd = col & 63;
                unsigned short* base = (unsigned short*)Cout + (size_t)(bx * Hh + h) * (Sq * HD);
                if (mode == 1) {
                    uint32_t* qh = (uint32_t*)base;
                    size_t qi = (((size_t)(s0 >> 4) * 4 + (hd >> 4)) * 32 + lane) * 4
                              + ((hd >> 3) & 1) * 2;
                    qh[qi]     = pkh2(a0, a1);
                    qh[qi + 1] = pkh2(a2, a3);
                } else if (mode == 2) {
                    uint32_t* kh = (uint32_t*)base;
                    int e = (hd >> 3) & 1;
                    kh[(((size_t)(s0 >> 3) * 4 + (hd >> 4)) * 32 + lane) * 2 + e] = pkh2(a0, a1);
                    kh[((((size_t)(s0 >> 3) + 1) * 4 + (hd >> 4)) * 32 + lane) * 2 + e] = pkh2(a2, a3);
                    if (klast && s0 + 8 == Sq - 1)
                        *(float2*)&klast[bx * DM + col] = make_float2(a2, a3);
                } else {
                    base[vfrag16(s0, col & 63)]           = __half_as_ushort(__float2half_rn(a0));
                    base[vfrag16(s0, (col & 63) + 1)]     = __half_as_ushort(__float2half_rn(a1));
                    base[vfrag16(s0 + 8, col & 63)]       = __half_as_ushort(__float2half_rn(a2));
                    base[vfrag16(s0 + 8, (col & 63) + 1)] = __half_as_ushort(__float2half_rn(a3));
                }
            }
        }
    }
}

__global__ void __launch_bounds__(256, 2) gemm_qkv(const unsigned short* __restrict__ A,
                                                   const unsigned short* __restrict__ WT,
                                                   unsigned short* q, unsigned short* k,
                                                   unsigned short* v, float* klast)
{
    extern __shared__ float dsm[];
    int z = blockIdx.z;
    unsigned short* C = (z == 0) ? q : (z == 1) ? k : v;
    gemm_body(A, WT + (size_t)z * DM * DM, C, z + 1, (z == 1) ? klast : (float*)0, dsm);
}

__global__ void __launch_bounds__(256, 2) gemm_o(const unsigned short* __restrict__ A,
                                                 const unsigned short* __restrict__ WT,
                                                 float* __restrict__ C)
{
    extern __shared__ float dsm[];
    gemm_body(A, WT, C, 0, (float*)0, dsm);
}

// ---------------- retrieval: sims (warp per event) ------------------------
__global__ __launch_bounds__(256) void retrieve_sims(const float* __restrict__ klast,
                                                     const float* __restrict__ events,
                                                     float* __restrict__ sims)
{
    int b = blockIdx.y;
    int tid = threadIdx.x;
    int lane = tid & 31, wid = tid >> 5;
    __shared__ float qs[DM];
    __shared__ float qn_s;

    for (int d = tid; d < DM; d += 256) qs[d] = klast[b * DM + d];
    __syncthreads();
    if (wid == 0) {
        float ps = 0.f;
        for (int d = lane * 4; d < DM; d += 128) {
            float4 t = *(const float4*)&qs[d];
            ps += t.x * t.x + t.y * t.y + t.z * t.z + t.w * t.w;
        }
#pragma unroll
        for (int off = 16; off > 0; off >>= 1) ps += __shfl_down_sync(0xffffffffu, ps, off);
        if (lane == 0) qn_s = sqrtf(ps) + 1e-8f;
    }
    __syncthreads();
    float qnorm = qn_s;

    int e = blockIdx.x * 8 + wid;
    if (e >= MEMN) return;
    const float* ep = events + (size_t)e * DM;
    float dot = 0.f, nn = 0.f;
    for (int d = lane * 4; d < DM; d += 128) {
        float4 ev = *(const float4*)(ep + d);
        float4 qv = *(const float4*)&qs[d];
        dot += qv.x * ev.x + qv.y * ev.y + qv.z * ev.z + qv.w * ev.w;
        nn  += ev.x * ev.x + ev.y * ev.y + ev.z * ev.z + ev.w * ev.w;
    }
#pragma unroll
    for (int off = 16; off > 0; off >>= 1) {
        dot += __shfl_down_sync(0xffffffffu, dot, off);
        nn  += __shfl_down_sync(0xffffffffu, nn, off);
    }
    if (lane == 0) sims[b * MEMN + e] = dot / (qnorm * (sqrtf(nn) + 1e-8f));
}

// ---------------- retrieval: parallel top-k + gather (raw fp32) ------------
__global__ __launch_bounds__(256) void topk_gather(const float* __restrict__ sims,
                                                   const float* __restrict__ events,
                                                   float* __restrict__ ret)
{
    int b = blockIdx.x;
    int tid = threadIdx.x;
    int lane = tid & 31, wid = tid >> 5;
    __shared__ float sv[MEMN];
    __shared__ float wmax[8];
    __shared__ int   widx[8];
    __shared__ int   tidx[KTOT];

    for (int e = tid; e < MEMN; e += 256) sv[e] = sims[b * MEMN + e];
    __syncthreads();

    for (int kk = 0; kk < KTOT; kk++) {
        float bm = -1e30f; int bi = MEMN;
        for (int e = tid; e < MEMN; e += 256) {
            float v = sv[e];
            if (v > bm || (v == bm && e < bi)) { bm = v; bi = e; }
        }
#pragma unroll
        for (int off = 16; off > 0; off >>= 1) {
            float om = __shfl_down_sync(0xffffffffu, bm, off);
            int   oi = __shfl_down_sync(0xffffffffu, bi, off);
            if (om > bm || (om == bm && oi < bi)) { bm = om; bi = oi; }
        }
        if (lane == 0) { wmax[wid] = bm; widx[wid] = bi; }
        __syncthreads();
        if (tid == 0) {
            float gm = wmax[0]; int gi = widx[0];
            for (int w = 1; w < 8; w++) {
                if (wmax[w] > gm || (wmax[w] == gm && widx[w] < gi)) { gm = wmax[w]; gi = widx[w]; }
            }
            tidx[kk] = gi;
            sv[gi] = -1e30f;
        }
        __syncthreads();
    }

    for (int kk = 0; kk < KTOT; kk++) {
        int src = tidx[kk];
        for (int d = tid; d < DM; d += 256)
            ret[((size_t)b * KTOT + kk) * DM + d] = events[(size_t)src * DM + d];
    }
}

// ---------------- flash v12: fp16 mma, 32-key tiles, safe tail wait --------
#define TKF 32
// smem (bytes): K2 4x4KB | V2 4x4KB | Km 2KB | Vm 2KB | CB 512B
#define OFFB_K2 0
#define OFFB_V2 16384
#define OFFB_KM 32768
#define OFFB_VM 34816
#define OFFB_CB 36864
#define FSMEM_BYTES (OFFB_CB + 512)

__global__ void __launch_bounds__(256, 2) flash_mma(const float* __restrict__ amask,
                                                    const unsigned short* __restrict__ qh,
                                                    const unsigned short* __restrict__ kh,
                                                    const unsigned short* __restrict__ vh,
                                                    const float* __restrict__ ret,
                                                    unsigned short* __restrict__ att)
{
    extern __shared__ float fsm[];
    unsigned short* KmH = (unsigned short*)((char*)fsm + OFFB_KM);
    unsigned short* VmH = (unsigned short*)((char*)fsm + OFFB_VM);
    float* CB = (float*)((char*)fsm + OFFB_CB);
    uint32_t sbase = smem_u32(fsm);

    int qt = gridDim.x - 1 - blockIdx.x;   // heavy tiles first
    int h = blockIdx.y, b = blockIdx.z;
    int tid = threadIdx.x;
    int lane = tid & 31, w = tid >> 5;
    int r = lane >> 2, cc = lane & 3;
    int i0 = qt * 128;
    const float scale = 0.125f;
    float slope = exp2f(-0.5f * (float)(h + 1));

    const char* kbc = (const char*)(kh + (size_t)(b * Hh + h) * (Sq * HD));
    const char* vbc = (const char*)(vh + (size_t)(b * Hh + h) * (Sq * HD));

    int ntiles = 4 * qt + 4;

    // ---- prologue: stage K/V tiles 0..2 (4KB each, 1 cpa16/thread) ----
    uint32_t dK0 = sbase + OFFB_K2 + (uint32_t)tid * 16;
    uint32_t dV0 = sbase + OFFB_V2 + (uint32_t)tid * 16;
#pragma unroll
    for (int s = 0; s < 3; s++) {
        cpa16(dK0 + s * 4096, kbc + (size_t)s * 4096 + tid * 16);
        cpa16(dV0 + s * 4096, vbc + (size_t)s * 4096 + tid * 16);
        CP_COMMIT();
    }
    if (tid < 96) CB[tid] = (1.0f - amask[b * Sq + tid]) * (-1e9f);

    // ---- Q fragments into registers (coalesced from frag-major) ----
    uint4 aq[4];
    {
        const uint4* qg = (const uint4*)(qh + (size_t)(b * Hh + h) * (Sq * HD)
                                         + (size_t)qt * 8192);
#pragma unroll
        for (int kt = 0; kt < 4; kt++) aq[kt] = qg[(w * 4 + kt) * 32 + lane];
    }

    // ---- memory tile (10 keys + 6 pad) into fp16 frag side buffers ----
    if (tid < 128) {
        int kk = tid >> 3, dseg = (tid & 7) * 8;
        const float* rp = ret + ((size_t)b * KTOT + kk) * DM + h * HD + dseg;
#pragma unroll
        for (int i = 0; i < 8; i++) {
            int d = dseg + i;
            float vv = (kk < KTOT) ? rp[i] : 0.f;
            unsigned short hv = __half_as_ushort(__float2half_rn(vv));
            KmH[((((kk >> 3) * 4 + (d >> 4)) * 32 + (kk & 7) * 4 + ((d & 7) >> 1)) * 2
                 + ((d >> 3) & 1)) * 2 + (d & 1)] = hv;
            VmH[(((d >> 3) * 32 + (d & 7) * 4 + ((kk & 7) >> 1)) * 2
                 + ((kk >> 3) & 1)) * 2 + (kk & 1)] = hv;
        }
    }
    __syncthreads();

    int row_lo = w * 16 + r;
    int ig_lo = i0 + row_lo, ig_hi = ig_lo + 8;

    const uint2* Km2 = (const uint2*)((char*)fsm + OFFB_KM);
    const uint2* Vm2 = (const uint2*)((char*)fsm + OFFB_VM);

    float of[8][4];
#pragma unroll
    for (int f = 0; f < 8; f++)
#pragma unroll
        for (int e = 0; e < 4; e++) of[f][e] = 0.f;
    float m_lo = -1e30f, m_hi = -1e30f, l_lo = 0.f, l_hi = 0.f;

    // ================= memory pass (16 cols) =================
    {
        float sc[2][4];
#pragma unroll
        for (int f = 0; f < 2; f++)
#pragma unroll
            for (int e = 0; e < 4; e++) sc[f][e] = 0.f;
#pragma unroll
        for (int kt = 0; kt < 4; kt++) {
#pragma unroll
            for (int f = 0; f < 2; f++) {
                uint2 bb = Km2[(f * 4 + kt) * 32 + lane];
                mma16(sc[f], (const uint32_t*)&aq[kt], (const uint32_t*)&bb);
            }
        }
        float tl = m_lo, th = m_hi;
#pragma unroll
        for (int f = 0; f < 2; f++) {
            int c0 = f * 8 + 2 * cc;
            float cb0  = (c0 < KTOT) ? 0.f : -1e30f;
            float cb1v = ((c0 + 1) < KTOT) ? 0.f : -1e30f;
            sc[f][0] = fmaf(sc[f][0], scale, cb0);
            sc[f][1] = fmaf(sc[f][1], scale, cb1v);
            sc[f][2] = fmaf(sc[f][2], scale, cb0);
            sc[f][3] = fmaf(sc[f][3], scale, cb1v);
            tl = fmaxf(tl, fmaxf(sc[f][0], sc[f][1]));
            th = fmaxf(th, fmaxf(sc[f][2], sc[f][3]));
        }
        tl = fmaxf(tl, __shfl_xor_sync(0xffffffffu, tl, 1));
        tl = fmaxf(tl, __shfl_xor_sync(0xffffffffu, tl, 2));
        th = fmaxf(th, __shfl_xor_sync(0xffffffffu, th, 1));
        th = fmaxf(th, __shfl_xor_sync(0xffffffffu, th, 2));
        float corr_lo = __expf(m_lo - tl), corr_hi = __expf(m_hi - th);
        l_lo *= corr_lo; l_hi *= corr_hi;
        m_lo = tl; m_hi = th;
        float sl = 0.f, sh = 0.f;
#pragma unroll
        for (int f = 0; f < 2; f++) {
            sc[f][0] = __expf(sc[f][0] - m_lo); sl += sc[f][0];
            sc[f][1] = __expf(sc[f][1] - m_lo); sl += sc[f][1];
            sc[f][2] = __expf(sc[f][2] - m_hi); sh += sc[f][2];
            sc[f][3] = __expf(sc[f][3] - m_hi); sh += sc[f][3];
        }
        sl += __shfl_xor_sync(0xffffffffu, sl, 1);
        sl += __shfl_xor_sync(0xffffffffu, sl, 2);
        sh += __shfl_xor_sync(0xffffffffu, sh, 1);
        sh += __shfl_xor_sync(0xffffffffu, sh, 2);
        l_lo += sl; l_hi += sh;
#pragma unroll
        for (int f = 0; f < 8; f++) {
            of[f][0] *= corr_lo; of[f][1] *= corr_lo;
            of[f][2] *= corr_hi; of[f][3] *= corr_hi;
        }
        // P reuse: C-frag == A-frag layout in fp16; pack pairs, no shuffle
        uint32_t ap[4];
        ap[0] = pkh2(sc[0][0], sc[0][1]);
        ap[1] = pkh2(sc[0][2], sc[0][3]);
        ap[2] = pkh2(sc[1][0], sc[1][1]);
        ap[3] = pkh2(sc[1][2], sc[1][3]);
#pragma unroll
        for (int f = 0; f < 8; f++) {
            uint2 bv = Vm2[f * 32 + lane];
            mma16(of[f], ap, (const uint32_t*)&bv);
        }
    }

    // ================= seq tiles (quad-buffered, safe tail wait) ============
    for (int t = 0; t < ntiles; ++t) {
        int buf = t & 3;
        int j0 = t * TKF;
        if (t + 2 < ntiles)      asm volatile("cp.async.wait_group 2;" ::: "memory");
        else if (t + 1 < ntiles) asm volatile("cp.async.wait_group 1;" ::: "memory");
        else                     asm volatile("cp.async.wait_group 0;" ::: "memory");
        __syncthreads();
        if (t + 3 < ntiles) {
            int tn = t + 3, bufn = tn & 3;
            cpa16(dK0 + bufn * 4096, kbc + (size_t)tn * 4096 + tid * 16);
            cpa16(dV0 + bufn * 4096, vbc + (size_t)tn * 4096 + tid * 16);
            CP_COMMIT();
            if (tid < TKF)
                CB[bufn * 32 + tid] = (1.0f - amask[b * Sq + tn * TKF + tid]) * (-1e9f);
        }
        const uint2* Ks2 = (const uint2*)((char*)fsm + OFFB_K2 + buf * 4096);
        const uint2* Vs2 = (const uint2*)((char*)fsm + OFFB_V2 + buf * 4096);
        const float* cb = CB + buf * 32;

        float sc[4][4];
#pragma unroll
        for (int f = 0; f < 4; f++)
#pragma unroll
            for (int e = 0; e < 4; e++) sc[f][e] = 0.f;
#pragma unroll
        for (int kt = 0; kt < 4; kt++) {
#pragma unroll
            for (int f = 0; f < 4; f++) {
                uint2 bb = Ks2[(f * 4 + kt) * 32 + lane];
                mma16(sc[f], (const uint32_t*)&aq[kt], (const uint32_t*)&bb);
            }
        }

        bool causal = (t >= 4 * qt);
        float o0f = (float)(2 * cc);
        float tl = m_lo, th = m_hi;
#pragma unroll
        for (int f = 0; f < 4; f++) {
            int c0 = f * 8 + 2 * cc;
            float cb0 = cb[c0], cb1v = cb[c0 + 1];
            float fl = (float)(ig_lo - j0 - f * 8);
            float s00 = fmaf(sc[f][0], scale, fmaf(slope, fl - o0f, cb0));
            float s01 = fmaf(sc[f][1], scale, fmaf(slope, fl - o0f - 1.0f, cb1v));
            float s10 = fmaf(sc[f][2], scale, fmaf(slope, fl + 8.0f - o0f, cb0));
            float s11 = fmaf(sc[f][3], scale, fmaf(slope, fl + 8.0f - o0f - 1.0f, cb1v));
            if (causal) {
                int jg0 = j0 + c0;
                if (jg0 > ig_lo)     s00 = -1e30f;
                if (jg0 + 1 > ig_lo) s01 = -1e30f;
                if (jg0 > ig_hi)     s10 = -1e30f;
                if (jg0 + 1 > ig_hi) s11 = -1e30f;
            }
            sc[f][0] = s00; sc[f][1] = s01; sc[f][2] = s10; sc[f][3] = s11;
            tl = fmaxf(tl, fmaxf(s00, s01));
            th = fmaxf(th, fmaxf(s10, s11));
        }
        tl = fmaxf(tl, __shfl_xor_sync(0xffffffffu, tl, 1));
        tl = fmaxf(tl, __shfl_xor_sync(0xffffffffu, tl, 2));
        th = fmaxf(th, __shfl_xor_sync(0xffffffffu, th, 1));
        th = fmaxf(th, __shfl_xor_sync(0xffffffffu, th, 2));

        float corr_lo = __expf(m_lo - tl), corr_hi = __expf(m_hi - th);
        l_lo *= corr_lo; l_hi *= corr_hi;
        m_lo = tl; m_hi = th;

        float sl = 0.f, sh = 0.f;
#pragma unroll
        for (int f = 0; f < 4; f++) {
            sc[f][0] = __expf(sc[f][0] - m_lo); sl += sc[f][0];
            sc[f][1] = __expf(sc[f][1] - m_lo); sl += sc[f][1];
            sc[f][2] = __expf(sc[f][2] - m_hi); sh += sc[f][2];
            sc[f][3] = __expf(sc[f][3] - m_hi); sh += sc[f][3];
        }
        sl += __shfl_xor_sync(0xffffffffu, sl, 1);
        sl += __shfl_xor_sync(0xffffffffu, sl, 2);
        sh += __shfl_xor_sync(0xffffffffu, sh, 1);
        sh += __shfl_xor_sync(0xffffffffu, sh, 2);
        l_lo += sl; l_hi += sh;

#pragma unroll
        for (int f = 0; f < 8; f++) {
            of[f][0] *= corr_lo; of[f][1] *= corr_lo;
            of[f][2] *= corr_hi; of[f][3] *= corr_hi;
        }

        // P reuse: pack C-frags directly as fp16 A-frags
#pragma unroll
        for (int kt = 0; kt < 2; kt++) {
            uint32_t ap[4];
            ap[0] = pkh2(sc[2 * kt][0],     sc[2 * kt][1]);
            ap[1] = pkh2(sc[2 * kt][2],     sc[2 * kt][3]);
            ap[2] = pkh2(sc[2 * kt + 1][0], sc[2 * kt + 1][1]);
            ap[3] = pkh2(sc[2 * kt + 1][2], sc[2 * kt + 1][3]);
#pragma unroll
            for (int f = 0; f < 8; f++) {
                uint2 bv = Vs2[(kt * 8 + f) * 32 + lane];
                mma16(of[f], ap, (const uint32_t*)&bv);
            }
        }
    }

    // ---- finalize: divide by l, fp16 A-frag store for gemm_o ----
    float inv_lo = 1.0f / l_lo, inv_hi = 1.0f / l_hi;
    int mlo = b * Sq + ig_lo;
    uint32_t* atth = (uint32_t*)att;
#pragma unroll
    for (int f = 0; f < 8; f++) {
        int k0 = h * HD + f * 8 + 2 * cc;
        size_t ai = (((size_t)(mlo >> 4) * 64 + (k0 >> 4)) * 32 + lane) * 4
                  + ((k0 >> 3) & 1) * 2;
        atth[ai]     = pkh2(of[f][0] * inv_lo, of[f][1] * inv_lo);
        atth[ai + 1] = pkh2(of[f][2] * inv_hi, of[f][3] * inv_hi);
    }
}

// ---------------- launcher ----------------
extern "C" void kernel_launch(void* const* d_in, const int* in_sizes, int n_in,
                              void* d_out, int out_size)
{
    const float* inputs = (const float*)d_in[0];
    const float* amask  = (const float*)d_in[1];
    const float* Wq     = (const float*)d_in[2];
    const float* Wk     = (const float*)d_in[3];
    const float* Wv     = (const float*)d_in[4];
    const float* Wo     = (const float*)d_in[5];
    const float* events = (const float*)d_in[6];
    float* out = (float*)d_out;

    unsigned short *q, *k, *v, *att, *wt, *ai;
    float *ret, *sims, *klast;
    cudaGetSymbolAddress((void**)&q,     g_q);
    cudaGetSymbolAddress((void**)&k,     g_k);
    cudaGetSymbolAddress((void**)&v,     g_v);
    cudaGetSymbolAddress((void**)&att,   g_att);
    cudaGetSymbolAddress((void**)&ret,   g_ret);
    cudaGetSymbolAddress((void**)&sims,  g_sims);
    cudaGetSymbolAddress((void**)&wt,    g_wt);
    cudaGetSymbolAddress((void**)&ai,    g_ai);
    cudaGetSymbolAddress((void**)&klast, g_klast);

    cudaFuncSetAttribute(gemm_qkv,  cudaFuncAttributeMaxDynamicSharedMemorySize, GSMEM_BYTES);
    cudaFuncSetAttribute(gemm_o,    cudaFuncAttributeMaxDynamicSharedMemorySize, GSMEM_BYTES);
    cudaFuncSetAttribute(flash_mma, cudaFuncAttributeMaxDynamicSharedMemorySize, FSMEM_BYTES);

    prep_a<<<(Bq * Sq / 16) * (DM / 16) * 32 / 256, 256>>>(inputs, ai);
    transpose_w<<<dim3(32, 32, 4), 256>>>(Wq, Wk, Wv, Wo, wt);

    gemm_qkv<<<dim3(8, 32, 3), 256, GSMEM_BYTES>>>(ai, wt, q, k, v, klast);

    retrieve_sims<<<dim3(125, Bq), 256>>>(klast, events, sims);
    topk_gather<<<Bq, 256>>>(sims, events, ret);

    flash_mma<<<dim3(Sq / 128, Hh, Bq), 256, FSMEM_BYTES>>>(amask, q, k, v, ret, att);

    gemm_o<<<dim3(8, 32), 256, GSMEM_BYTES>>>(att, wt + 3 * (size_t)DM * DM, out);
}